// round 4
// baseline (speedup 1.0000x reference)
#include <cuda_runtime.h>

#define N_BATCH 8
#define C 256
#define HW 1024
#define CPG 32
#define NH 32
#define D 8
#define THREE_C 768

// Scratch (static __device__ arrays: allocation-free per harness rules)
__device__ float g_xn[N_BATCH * C * HW];        // 8 MB
__device__ float g_qkv[N_BATCH * THREE_C * HW]; // 24 MB
__device__ float g_y[N_BATCH * C * HW];         // 8 MB

// ---------------------------------------------------------------------------
// Kernel 1: GroupNorm (8 groups of 32 channels x 1024). One block per (n,g).
// ---------------------------------------------------------------------------
__global__ void gn_kernel(const float* __restrict__ x,
                          const float* __restrict__ gn_w,
                          const float* __restrict__ gn_b) {
    int n = blockIdx.x >> 3;
    int g = blockIdx.x & 7;
    const float4* xp = (const float4*)(x + (size_t)(n * C + g * CPG) * HW);
    float4* op = (float4*)(g_xn + (size_t)(n * C + g * CPG) * HW);

    float s = 0.f, ss = 0.f;
#pragma unroll 4
    for (int i = threadIdx.x; i < 8192; i += 256) {
        float4 v = xp[i];
        s  += v.x + v.y + v.z + v.w;
        ss += v.x * v.x + v.y * v.y + v.z * v.z + v.w * v.w;
    }
#pragma unroll
    for (int off = 16; off; off >>= 1) {
        s  += __shfl_down_sync(0xffffffffu, s, off);
        ss += __shfl_down_sync(0xffffffffu, ss, off);
    }
    __shared__ float rs[8], rss[8];
    __shared__ float s_mu, s_rinv;
    int warp = threadIdx.x >> 5, lane = threadIdx.x & 31;
    if (lane == 0) { rs[warp] = s; rss[warp] = ss; }
    __syncthreads();
    if (threadIdx.x == 0) {
        float ts = 0.f, tss = 0.f;
#pragma unroll
        for (int w = 0; w < 8; ++w) { ts += rs[w]; tss += rss[w]; }
        float mu  = ts * (1.f / 32768.f);
        float var = tss * (1.f / 32768.f) - mu * mu;
        s_mu = mu;
        s_rinv = rsqrtf(var + 1e-5f);
    }
    __syncthreads();
    float mu = s_mu, rinv = s_rinv;
#pragma unroll 4
    for (int i = threadIdx.x; i < 8192; i += 256) {
        int cl = i >> 8;  // 256 float4 per channel
        float w = __ldg(&gn_w[g * CPG + cl]) * rinv;
        float b = __ldg(&gn_b[g * CPG + cl]) - mu * w;
        float4 v = xp[i];
        float4 o;
        o.x = v.x * w + b; o.y = v.y * w + b;
        o.z = v.z * w + b; o.w = v.w * w + b;
        op[i] = o;
    }
}

// ---------------------------------------------------------------------------
// Kernel 2/4: batched GEMM  Out[n][o][t] = sum_c W[o][c]*In[n][c][t] + bias[o]
// (+ optional residual X). K = 256 always. Tile 64x64, BK=32, 4x4/thread.
// ---------------------------------------------------------------------------
template <bool RESIDUAL>
__global__ void gemm_kernel(const float* __restrict__ W,
                            const float* __restrict__ bias,
                            const float* __restrict__ In,
                            const float* __restrict__ X,
                            float* __restrict__ Out, int M) {
    __shared__ float As[32][68];  // A transposed [c][o], pad to kill conflicts
    __shared__ float Bs[32][64];

    int n  = blockIdx.z;
    int mo = blockIdx.y * 64;
    int to = blockIdx.x * 64;
    int tid = threadIdx.x;
    int tm = tid >> 4, tn = tid & 15;

    const float* Wp = W + (size_t)mo * C;
    const float* Ip = In + (size_t)n * (C * HW) + to;

    float acc[4][4];
#pragma unroll
    for (int i = 0; i < 4; ++i)
#pragma unroll
        for (int j = 0; j < 4; ++j) acc[i][j] = 0.f;

    for (int k0 = 0; k0 < C; k0 += 32) {
#pragma unroll
        for (int i = 0; i < 8; ++i) {
            int idx = i * 256 + tid;
            int o = idx >> 5, c = idx & 31;
            As[c][o] = Wp[o * C + k0 + c];
        }
#pragma unroll
        for (int i = 0; i < 8; ++i) {
            int idx = i * 256 + tid;
            int c = idx >> 6, t = idx & 63;
            Bs[c][t] = Ip[(k0 + c) * HW + t];
        }
        __syncthreads();
#pragma unroll
        for (int k = 0; k < 32; ++k) {
            float4 a = *(const float4*)&As[k][tm * 4];
            float4 b = *(const float4*)&Bs[k][tn * 4];
            acc[0][0] += a.x * b.x; acc[0][1] += a.x * b.y;
            acc[0][2] += a.x * b.z; acc[0][3] += a.x * b.w;
            acc[1][0] += a.y * b.x; acc[1][1] += a.y * b.y;
            acc[1][2] += a.y * b.z; acc[1][3] += a.y * b.w;
            acc[2][0] += a.z * b.x; acc[2][1] += a.z * b.y;
            acc[2][2] += a.z * b.z; acc[2][3] += a.z * b.w;
            acc[3][0] += a.w * b.x; acc[3][1] += a.w * b.y;
            acc[3][2] += a.w * b.z; acc[3][3] += a.w * b.w;
        }
        __syncthreads();
    }
#pragma unroll
    for (int i = 0; i < 4; ++i) {
        int o = mo + tm * 4 + i;
        float bi = __ldg(&bias[o]);
        size_t off = (size_t)(n * M + o) * HW + to + tn * 4;
        float4 r;
        r.x = acc[i][0] + bi; r.y = acc[i][1] + bi;
        r.z = acc[i][2] + bi; r.w = acc[i][3] + bi;
        if (RESIDUAL) {
            float4 xv = *(const float4*)(X + off);
            r.x += xv.x; r.y += xv.y; r.z += xv.z; r.w += xv.w;
        }
        *(float4*)(Out + off) = r;
    }
}

// ---------------------------------------------------------------------------
// Kernel 3: attention. Block = one (n, h, s-quarter). K,V (8x1024 fp32 each)
// fully resident in SMEM (64 KB). Each thread owns one s-row, one-pass online
// softmax (rescale only on max update — rare), y written to g_y.
// ---------------------------------------------------------------------------
__global__ void attn_kernel() {
    extern __shared__ float sm[];
    float* kT = sm;             // kT[t][8]
    float* vT = sm + HW * D;    // vT[t][8]

    int n = blockIdx.z, h = blockIdx.y;
    const float* base = g_qkv + (size_t)n * (THREE_C * HW);
    const float* qg = base + (h * D) * HW;
    const float* kg = base + (C + h * D) * HW;
    const float* vg = base + (2 * C + h * D) * HW;

#pragma unroll
    for (int i = 0; i < 32; ++i) {
        int idx = i * 256 + threadIdx.x;
        int d = idx >> 10, t = idx & 1023;
        kT[t * D + d] = kg[d * HW + t];
        vT[t * D + d] = vg[d * HW + t];
    }
    __syncthreads();

    int s = blockIdx.x * 256 + threadIdx.x;
    const float scale = 0.35355339059327373f;  // 1/sqrt(8)
    float q[8];
#pragma unroll
    for (int d = 0; d < 8; ++d) q[d] = qg[d * HW + s] * scale;

    float m = -1e30f, l = 0.f;
    float acc[8];
#pragma unroll
    for (int d = 0; d < 8; ++d) acc[d] = 0.f;

    const float4* k4 = (const float4*)kT;
    const float4* v4 = (const float4*)vT;

#pragma unroll 4
    for (int t = 0; t < HW; ++t) {
        float4 ka = k4[2 * t], kb = k4[2 * t + 1];
        float sc = q[0] * ka.x + q[1] * ka.y + q[2] * ka.z + q[3] * ka.w
                 + q[4] * kb.x + q[5] * kb.y + q[6] * kb.z + q[7] * kb.w;
        if (sc > m) {
            float corr = __expf(m - sc);  // first iter: exp(-huge) = 0
            l *= corr;
#pragma unroll
            for (int d = 0; d < 8; ++d) acc[d] *= corr;
            m = sc;
        }
        float e = __expf(sc - m);
        l += e;
        float4 va = v4[2 * t], vb = v4[2 * t + 1];
        acc[0] += e * va.x; acc[1] += e * va.y;
        acc[2] += e * va.z; acc[3] += e * va.w;
        acc[4] += e * vb.x; acc[5] += e * vb.y;
        acc[6] += e * vb.z; acc[7] += e * vb.w;
    }

    float inv = 1.f / l;
    float* yp = g_y + (size_t)(n * C + h * D) * HW + s;
#pragma unroll
    for (int d = 0; d < 8; ++d) yp[d * HW] = acc[d] * inv;
}

// ---------------------------------------------------------------------------
extern "C" void kernel_launch(void* const* d_in, const int* in_sizes, int n_in,
                              void* d_out, int out_size) {
    const float* x     = (const float*)d_in[0];
    const float* gn_w  = (const float*)d_in[1];
    const float* gn_b  = (const float*)d_in[2];
    const float* qkv_w = (const float*)d_in[3];
    const float* qkv_b = (const float*)d_in[4];
    const float* out_w = (const float*)d_in[5];
    const float* out_b = (const float*)d_in[6];
    float* out = (float*)d_out;

    float *p_xn, *p_qkv_unused, *p_y;
    cudaGetSymbolAddress((void**)&p_xn, g_xn);
    cudaGetSymbolAddress((void**)&p_qkv_unused, g_qkv);
    cudaGetSymbolAddress((void**)&p_y, g_y);

    // 1. GroupNorm -> g_xn
    gn_kernel<<<64, 256>>>(x, gn_w, gn_b);

    // 2. QKV GEMM: g_qkv[n][768][1024]
    gemm_kernel<false><<<dim3(16, 12, 8), 256>>>(
        qkv_w, qkv_b, p_xn, nullptr, p_qkv_unused, THREE_C);

    // 3. Attention -> g_y
    cudaFuncSetAttribute(attn_kernel,
                         cudaFuncAttributeMaxDynamicSharedMemorySize, 65536);
    attn_kernel<<<dim3(4, NH, 8), 256, 65536>>>();

    // 4. Output projection + residual -> d_out
    gemm_kernel<true><<<dim3(16, 4, 8), 256>>>(
        out_w, out_b, p_y, x, out, C);
}